// round 8
// baseline (speedup 1.0000x reference)
#include <cuda_runtime.h>
#include <cstdint>

// Problem constants
#define C_DIM   384
#define N_DIM   1152
#define B_SZ    8
#define H_IMG   224
#define W_IMG   224
#define HWB     50176
#define M_TOT   401408
#define HD      96
#define NHEADS  4

// QKV scratch in fp16 (half2 words): [M_TOT][576 words]; q pre-scaled by 96^-0.5
__device__ uint32_t g_qkvh[(size_t)M_TOT * 576];
// Pre-converted W in fp16 (half2 words): [1152][384] halves
__device__ uint32_t g_wh[221184];

__device__ __forceinline__ uint32_t pack_h2(float lo, float hi) {
    uint32_t r;
    asm("cvt.rn.f16x2.f32 %0, %1, %2;" : "=r"(r) : "f"(hi), "f"(lo));
    return r;   // d<15:0> = lo, d<31:16> = hi
}

__device__ __forceinline__ uint32_t smem_u32(const void* p) {
    uint32_t a;
    asm("{ .reg .u64 t; cvta.to.shared.u64 t, %1; cvt.u32.u64 %0, t; }"
        : "=r"(a) : "l"(p));
    return a;
}

__device__ __forceinline__ void ldsm_x4(uint32_t& r0, uint32_t& r1,
                                        uint32_t& r2, uint32_t& r3, uint32_t a) {
    asm volatile("ldmatrix.sync.aligned.m8n8.x4.shared.b16 {%0,%1,%2,%3}, [%4];"
                 : "=r"(r0), "=r"(r1), "=r"(r2), "=r"(r3) : "r"(a));
}
__device__ __forceinline__ void ldsm_x4_t(uint32_t& r0, uint32_t& r1,
                                          uint32_t& r2, uint32_t& r3, uint32_t a) {
    asm volatile("ldmatrix.sync.aligned.m8n8.x4.trans.shared.b16 {%0,%1,%2,%3}, [%4];"
                 : "=r"(r0), "=r"(r1), "=r"(r2), "=r"(r3) : "r"(a));
}

__device__ __forceinline__ void mma_f16(float& c0, float& c1, float& c2, float& c3,
                                        uint32_t a0, uint32_t a1, uint32_t a2, uint32_t a3,
                                        uint32_t b0, uint32_t b1) {
    asm volatile(
        "mma.sync.aligned.m16n8k16.row.col.f32.f16.f16.f32 "
        "{%0,%1,%2,%3}, {%4,%5,%6,%7}, {%8,%9}, {%0,%1,%2,%3};"
        : "+f"(c0), "+f"(c1), "+f"(c2), "+f"(c3)
        : "r"(a0), "r"(a1), "r"(a2), "r"(a3), "r"(b0), "r"(b1));
}

// ---------------------------------------------------------------------------
// Kernel 0: one-time W fp32 -> fp16 conversion
// ---------------------------------------------------------------------------
__global__ void __launch_bounds__(256) wconv(const float* __restrict__ w)
{
    int i = blockIdx.x * 256 + threadIdx.x;
    if (i < 110592) {
        float4 v = ((const float4*)w)[i];
        uint2 o;
        o.x = pack_h2(v.x, v.y);
        o.y = pack_h2(v.z, v.w);
        ((uint2*)g_wh)[i] = o;
    }
}

// ---------------------------------------------------------------------------
// Kernel 1: QKV GEMM (Round-6 schedule; fp16 output, q pre-scaled)
// ---------------------------------------------------------------------------
#define ASTH 136
#define BSTH 40
#define AS_BYTES (384 * ASTH * 2)
#define QKV_SMEM (AS_BYTES + 128 * BSTH * 2)

__global__ void __launch_bounds__(256, 2) qkv_mma(
    const float* __restrict__ x,
    const float* __restrict__ bias)
{
    extern __shared__ char smem[];
    const uint32_t abase = smem_u32(smem);
    const uint32_t bbase = abase + AS_BYTES;

    const int tid = threadIdx.x;
    const int wid = tid >> 5;
    const int lid = tid & 31;
    const int mw  = wid & 1;
    const int nw  = wid >> 1;
    const int lq  = lid >> 2;
    const int lr  = lid & 3;

    const int m0 = blockIdx.x * 128;
    const int b  = m0 / HWB;
    const float* xb = x + (size_t)b * C_DIM * HWB + (m0 - b * HWB);

    for (int i = tid; i < 12288; i += 256) {
        int k = i >> 5, m4 = i & 31;
        float4 v = *(const float4*)(xb + (size_t)k * HWB + m4 * 4);
        uint32_t h0 = pack_h2(v.x, v.y);
        uint32_t h1 = pack_h2(v.z, v.w);
        uint32_t dst = abase + (uint32_t)(k * ASTH + m4 * 4) * 2;
        asm volatile("st.shared.v2.b32 [%0], {%1,%2};" :: "r"(dst), "r"(h0), "r"(h1));
    }

    const uint32_t a_lane = (uint32_t)(((lid & 7) + ((lid >> 4) & 1) * 8) * (ASTH * 2)
                                       + (mw * 64 + ((lid >> 3) & 1) * 8) * 2);
    const uint32_t b_lane = (uint32_t)((nw * 32 + ((lid >> 4) & 1) * 8 + (lid & 7)) * (BSTH * 2)
                                       + ((lid >> 3) & 1) * 16);

    const int bs_n  = tid >> 1;
    const int bs_kb = (tid & 1) * 2;

    for (int nt = 0; nt < 9; ++nt) {
        const int n0 = nt * 128;
        float c[4][4][4];
        #pragma unroll
        for (int i = 0; i < 4; ++i)
            #pragma unroll
            for (int j = 0; j < 4; ++j)
                c[i][j][0] = c[i][j][1] = c[i][j][2] = c[i][j][3] = 0.f;

        for (int s = 0; s < 12; ++s) {
            __syncthreads();
            {
                const uint4* src = (const uint4*)(g_wh
                    + (size_t)(n0 + bs_n) * 192 + s * 16 + bs_kb * 4);
                uint4 v0 = src[0];
                uint4 v1 = src[1];
                uint32_t dst = bbase + (uint32_t)(bs_n * (BSTH * 2) + bs_kb * 16);
                asm volatile("st.shared.v4.b32 [%0], {%1,%2,%3,%4};"
                             :: "r"(dst), "r"(v0.x), "r"(v0.y), "r"(v0.z), "r"(v0.w));
                asm volatile("st.shared.v4.b32 [%0], {%1,%2,%3,%4};"
                             :: "r"(dst + 16), "r"(v1.x), "r"(v1.y), "r"(v1.z), "r"(v1.w));
            }
            __syncthreads();

            #pragma unroll
            for (int kc = 0; kc < 2; ++kc) {
                uint32_t a[4][4], bb[2][4];
                const uint32_t a_base = abase + a_lane
                    + (uint32_t)((s * 32 + kc * 16) * (ASTH * 2));
                #pragma unroll
                for (int i = 0; i < 4; ++i)
                    ldsm_x4_t(a[i][0], a[i][1], a[i][2], a[i][3],
                              a_base + (uint32_t)(i * 32));
                const uint32_t b_base = bbase + b_lane + (uint32_t)(kc * 32);
                #pragma unroll
                for (int jp = 0; jp < 2; ++jp)
                    ldsm_x4(bb[jp][0], bb[jp][1], bb[jp][2], bb[jp][3],
                            b_base + (uint32_t)(jp * 16 * (BSTH * 2)));
                #pragma unroll
                for (int i = 0; i < 4; ++i)
                    #pragma unroll
                    for (int j = 0; j < 4; ++j) {
                        const int jp = j >> 1, lo = (j & 1) * 2;
                        mma_f16(c[i][j][0], c[i][j][1], c[i][j][2], c[i][j][3],
                                a[i][0], a[i][1], a[i][2], a[i][3],
                                bb[jp][lo], bb[jp][lo + 1]);
                    }
            }
        }

        // ---- Epilogue: bias (+ q scale for n<384), fp16 stores ----
        const float qsc = (n0 < 384) ? 0.10206207261596577f : 1.0f;
        #pragma unroll
        for (int j = 0; j < 4; ++j) {
            const int gn = n0 + nw * 32 + j * 8 + lr * 2;
            float2 bv = *(const float2*)(bias + gn);
            const int gn2 = gn >> 1;
            #pragma unroll
            for (int i = 0; i < 4; ++i) {
                const int gm0 = m0 + mw * 64 + i * 16 + lq;
                uint32_t p0 = pack_h2((c[i][j][0] + bv.x) * qsc,
                                      (c[i][j][1] + bv.y) * qsc);
                uint32_t p1 = pack_h2((c[i][j][2] + bv.x) * qsc,
                                      (c[i][j][3] + bv.y) * qsc);
                g_qkvh[(size_t)gm0 * 576 + gn2]       = p0;
                g_qkvh[(size_t)(gm0 + 8) * 576 + gn2] = p1;
            }
        }
    }
}

// ---------------------------------------------------------------------------
// Kernel 2: tensor-core windowed attention (fp16 input; pure-copy prologue)
// ---------------------------------------------------------------------------
#define ROWB 208                      // bytes per Q/K/V row (104 halves)
#define MATB (64 * ROWB)              // 13312 bytes per matrix
#define AT_SMEM (3 * MATB)            // 39936

__global__ void __launch_bounds__(128) attn_tc(float* __restrict__ out)
{
    extern __shared__ char smem[];
    const uint32_t qb = smem_u32(smem);
    const uint32_t kb = qb + MATB;
    const uint32_t vb = kb + MATB;
    uint32_t* smw = (uint32_t*)smem;
    float* osm = (float*)smem;        // reused AFTER AV (post-sync)

    const int tid  = threadIdx.x;
    const int wrp  = tid >> 5;
    const int lid  = tid & 31;
    const int lam  = lid & 3;
    const int win  = blockIdx.x;
    const int head = blockIdx.y;
    const int b    = win >> 10;
    const int wh   = (win >> 5) & 31;
    const int ww   = win & 31;

    // Zero pad rows 49..63 of Q/K/V (52 words per row)
    for (int i = tid; i < 2340; i += 128) {
        int arr = i / 780, rem = i % 780;
        smw[arr * 3328 + (49 + rem / 52) * 52 + (rem % 52)] = 0u;
    }

    // Load Q/K/V: pure uint4 copy (q already scaled, all fp16)
    // 49 tokens x 3 segs x 12 uint4
    for (int e = tid; e < 1764; e += 128) {
        int tok = e / 36, r = e % 36;
        int seg = r / 12, f4 = r % 12;
        const uint4* src = (const uint4*)(g_qkvh
            + ((size_t)b * HWB + (wh * 7 + tok / 7) * W_IMG + ww * 7 + tok % 7) * 576
            + seg * 192 + head * 48 + f4 * 4);
        uint4 v = *src;
        uint32_t dst = qb + (uint32_t)(seg * MATB + tok * ROWB + f4 * 16);
        asm volatile("st.shared.v4.b32 [%0], {%1,%2,%3,%4};"
                     :: "r"(dst), "r"(v.x), "r"(v.y), "r"(v.z), "r"(v.w));
    }
    __syncthreads();

    // ---- Scores: S[q][key] = Q . K ----
    const int q0 = wrp * 16;
    const uint32_t a_addr = qb + (uint32_t)((q0 + (lid & 15)) * ROWB + (lid >> 4) * 16);
    const uint32_t k_rsel = (uint32_t)((((lid >> 4) & 1) * 8 + (lid & 7)) * ROWB
                                       + ((lid >> 3) & 1) * 16);
    float sc[7][4];
    #pragma unroll
    for (int t = 0; t < 7; ++t)
        sc[t][0] = sc[t][1] = sc[t][2] = sc[t][3] = 0.f;

    #pragma unroll
    for (int s = 0; s < 6; ++s) {
        uint32_t a0, a1, a2, a3;
        ldsm_x4(a0, a1, a2, a3, a_addr + (uint32_t)(s * 32));
        #pragma unroll
        for (int np = 0; np < 4; ++np) {
            uint32_t r0, r1, r2, r3;
            ldsm_x4(r0, r1, r2, r3, kb + k_rsel + (uint32_t)(np * 16 * ROWB + s * 32));
            mma_f16(sc[2*np][0], sc[2*np][1], sc[2*np][2], sc[2*np][3],
                    a0, a1, a2, a3, r0, r1);
            if (np < 3)
                mma_f16(sc[2*np+1][0], sc[2*np+1][1], sc[2*np+1][2], sc[2*np+1][3],
                        a0, a1, a2, a3, r2, r3);
        }
    }

    // ---- Softmax in registers ----
    float mx0 = -1e30f, mx1 = -1e30f;
    #pragma unroll
    for (int t = 0; t < 6; ++t) {
        mx0 = fmaxf(mx0, fmaxf(sc[t][0], sc[t][1]));
        mx1 = fmaxf(mx1, fmaxf(sc[t][2], sc[t][3]));
    }
    if (lam == 0) { mx0 = fmaxf(mx0, sc[6][0]); mx1 = fmaxf(mx1, sc[6][2]); }
    mx0 = fmaxf(mx0, __shfl_xor_sync(0xffffffffu, mx0, 1));
    mx0 = fmaxf(mx0, __shfl_xor_sync(0xffffffffu, mx0, 2));
    mx1 = fmaxf(mx1, __shfl_xor_sync(0xffffffffu, mx1, 1));
    mx1 = fmaxf(mx1, __shfl_xor_sync(0xffffffffu, mx1, 2));

    float pr[7][4];
    float sum0 = 0.f, sum1 = 0.f;
    #pragma unroll
    for (int t = 0; t < 6; ++t) {
        pr[t][0] = __expf(sc[t][0] - mx0);
        pr[t][1] = __expf(sc[t][1] - mx0);
        pr[t][2] = __expf(sc[t][2] - mx1);
        pr[t][3] = __expf(sc[t][3] - mx1);
        sum0 += pr[t][0] + pr[t][1];
        sum1 += pr[t][2] + pr[t][3];
    }
    pr[6][0] = (lam == 0) ? __expf(sc[6][0] - mx0) : 0.f;
    pr[6][1] = 0.f;
    pr[6][2] = (lam == 0) ? __expf(sc[6][2] - mx1) : 0.f;
    pr[6][3] = 0.f;
    sum0 += pr[6][0];
    sum1 += pr[6][2];
    sum0 += __shfl_xor_sync(0xffffffffu, sum0, 1);
    sum0 += __shfl_xor_sync(0xffffffffu, sum0, 2);
    sum1 += __shfl_xor_sync(0xffffffffu, sum1, 1);
    sum1 += __shfl_xor_sync(0xffffffffu, sum1, 2);
    const float inv0 = 1.f / sum0;
    const float inv1 = 1.f / sum1;

    // ---- AV: out = P . V ----
    float co[12][4];
    #pragma unroll
    for (int t = 0; t < 12; ++t)
        co[t][0] = co[t][1] = co[t][2] = co[t][3] = 0.f;

    const uint32_t v_rsel = (uint32_t)((lid & 15) * ROWB + ((lid >> 4) & 1) * 16);
    #pragma unroll
    for (int t = 0; t < 4; ++t) {
        uint32_t a0 = pack_h2(pr[2*t][0], pr[2*t][1]);
        uint32_t a1 = pack_h2(pr[2*t][2], pr[2*t][3]);
        uint32_t a2 = 0u, a3 = 0u;
        if (t < 3) {
            a2 = pack_h2(pr[2*t+1][0], pr[2*t+1][1]);
            a3 = pack_h2(pr[2*t+1][2], pr[2*t+1][3]);
        }
        #pragma unroll
        for (int np = 0; np < 6; ++np) {
            uint32_t r0, r1, r2, r3;
            ldsm_x4_t(r0, r1, r2, r3, vb + v_rsel + (uint32_t)(t * 16 * ROWB + np * 32));
            mma_f16(co[2*np][0], co[2*np][1], co[2*np][2], co[2*np][3],
                    a0, a1, a2, a3, r0, r1);
            mma_f16(co[2*np+1][0], co[2*np+1][1], co[2*np+1][2], co[2*np+1][3],
                    a0, a1, a2, a3, r2, r3);
        }
    }
    __syncthreads();

    // ---- Stage normalized output rows to osm[49][96] ----
    {
        const int r   = lid >> 2;
        const int rg0 = q0 + r;
        const int rg8 = q0 + r + 8;
        #pragma unroll
        for (int nt = 0; nt < 12; ++nt) {
            const int d = nt * 8 + 2 * lam;
            if (rg0 < 49)
                *(float2*)(osm + rg0 * 96 + d) =
                    make_float2(co[nt][0] * inv0, co[nt][1] * inv0);
            if (rg8 < 49)
                *(float2*)(osm + rg8 * 96 + d) =
                    make_float2(co[nt][2] * inv1, co[nt][3] * inv1);
        }
    }
    __syncthreads();

    // ---- Coalesced-ish global write (w-contiguous runs of 7) ----
    for (int e = tid; e < 4704; e += 128) {
        int tok = e % 49, d = e / 49;
        out[(((size_t)b * C_DIM + head * HD + d) * H_IMG + wh * 7 + tok / 7) * W_IMG
            + ww * 7 + tok % 7] = osm[tok * 96 + d];
    }
}

// ---------------------------------------------------------------------------
extern "C" void kernel_launch(void* const* d_in, const int* in_sizes, int n_in,
                              void* d_out, int out_size)
{
    const float* x    = (const float*)d_in[0];
    const float* w    = (const float*)d_in[1];
    const float* bias = (const float*)d_in[2];
    float* out        = (float*)d_out;

    cudaFuncSetAttribute(qkv_mma, cudaFuncAttributeMaxDynamicSharedMemorySize,
                         (int)QKV_SMEM);
    cudaFuncSetAttribute(attn_tc, cudaFuncAttributeMaxDynamicSharedMemorySize,
                         (int)AT_SMEM);

    wconv<<<432, 256>>>(w);
    qkv_mma<<<M_TOT / 128, 256, QKV_SMEM>>>(x, bias);
    attn_tc<<<dim3(B_SZ * 32 * 32, NHEADS), 128, AT_SMEM>>>(out);
}

// round 9
// speedup vs baseline: 1.0903x; 1.0903x over previous
#include <cuda_runtime.h>
#include <cstdint>

// Problem constants
#define C_DIM   384
#define N_DIM   1152
#define B_SZ    8
#define H_IMG   224
#define W_IMG   224
#define HWB     50176
#define M_TOT   401408
#define HD      96
#define NHEADS  4

// QKV scratch in fp16 (half2 words): [M_TOT][576 words]; q pre-scaled by 96^-0.5
__device__ uint32_t g_qkvh[(size_t)M_TOT * 576];
// Pre-converted W in fp16 (half2 words): [1152][384] halves
__device__ uint32_t g_wh[221184];

__device__ __forceinline__ uint32_t pack_h2(float lo, float hi) {
    uint32_t r;
    asm("cvt.rn.f16x2.f32 %0, %1, %2;" : "=r"(r) : "f"(hi), "f"(lo));
    return r;   // d<15:0> = lo, d<31:16> = hi
}

__device__ __forceinline__ uint32_t smem_u32(const void* p) {
    uint32_t a;
    asm("{ .reg .u64 t; cvta.to.shared.u64 t, %1; cvt.u32.u64 %0, t; }"
        : "=r"(a) : "l"(p));
    return a;
}

__device__ __forceinline__ void ldsm_x4(uint32_t& r0, uint32_t& r1,
                                        uint32_t& r2, uint32_t& r3, uint32_t a) {
    asm volatile("ldmatrix.sync.aligned.m8n8.x4.shared.b16 {%0,%1,%2,%3}, [%4];"
                 : "=r"(r0), "=r"(r1), "=r"(r2), "=r"(r3) : "r"(a));
}
__device__ __forceinline__ void ldsm_x4_t(uint32_t& r0, uint32_t& r1,
                                          uint32_t& r2, uint32_t& r3, uint32_t a) {
    asm volatile("ldmatrix.sync.aligned.m8n8.x4.trans.shared.b16 {%0,%1,%2,%3}, [%4];"
                 : "=r"(r0), "=r"(r1), "=r"(r2), "=r"(r3) : "r"(a));
}

__device__ __forceinline__ void mma_f16(float& c0, float& c1, float& c2, float& c3,
                                        uint32_t a0, uint32_t a1, uint32_t a2, uint32_t a3,
                                        uint32_t b0, uint32_t b1) {
    asm volatile(
        "mma.sync.aligned.m16n8k16.row.col.f32.f16.f16.f32 "
        "{%0,%1,%2,%3}, {%4,%5,%6,%7}, {%8,%9}, {%0,%1,%2,%3};"
        : "+f"(c0), "+f"(c1), "+f"(c2), "+f"(c3)
        : "r"(a0), "r"(a1), "r"(a2), "r"(a3), "r"(b0), "r"(b1));
}

// ---------------------------------------------------------------------------
// Kernel 0: one-time W fp32 -> fp16 conversion
// ---------------------------------------------------------------------------
__global__ void __launch_bounds__(256) wconv(const float* __restrict__ w)
{
    int i = blockIdx.x * 256 + threadIdx.x;
    if (i < 110592) {
        float4 v = ((const float4*)w)[i];
        uint2 o;
        o.x = pack_h2(v.x, v.y);
        o.y = pack_h2(v.z, v.w);
        ((uint2*)g_wh)[i] = o;
    }
}

// ---------------------------------------------------------------------------
// Kernel 1: QKV GEMM (Round-6 schedule; fp16 output via quad-transpose STG.128)
// ---------------------------------------------------------------------------
#define ASTH 136
#define BSTH 40
#define AS_BYTES (384 * ASTH * 2)
#define QKV_SMEM (AS_BYTES + 128 * BSTH * 2)

__global__ void __launch_bounds__(256, 2) qkv_mma(
    const float* __restrict__ x,
    const float* __restrict__ bias)
{
    extern __shared__ char smem[];
    const uint32_t abase = smem_u32(smem);
    const uint32_t bbase = abase + AS_BYTES;

    const int tid = threadIdx.x;
    const int wid = tid >> 5;
    const int lid = tid & 31;
    const int mw  = wid & 1;
    const int nw  = wid >> 1;
    const int lq  = lid >> 2;
    const int lr  = lid & 3;

    const int m0 = blockIdx.x * 128;
    const int b  = m0 / HWB;
    const float* xb = x + (size_t)b * C_DIM * HWB + (m0 - b * HWB);

    for (int i = tid; i < 12288; i += 256) {
        int k = i >> 5, m4 = i & 31;
        float4 v = *(const float4*)(xb + (size_t)k * HWB + m4 * 4);
        uint32_t h0 = pack_h2(v.x, v.y);
        uint32_t h1 = pack_h2(v.z, v.w);
        uint32_t dst = abase + (uint32_t)(k * ASTH + m4 * 4) * 2;
        asm volatile("st.shared.v2.b32 [%0], {%1,%2};" :: "r"(dst), "r"(h0), "r"(h1));
    }

    const uint32_t a_lane = (uint32_t)(((lid & 7) + ((lid >> 4) & 1) * 8) * (ASTH * 2)
                                       + (mw * 64 + ((lid >> 3) & 1) * 8) * 2);
    const uint32_t b_lane = (uint32_t)((nw * 32 + ((lid >> 4) & 1) * 8 + (lid & 7)) * (BSTH * 2)
                                       + ((lid >> 3) & 1) * 16);

    const int bs_n  = tid >> 1;
    const int bs_kb = (tid & 1) * 2;

    for (int nt = 0; nt < 9; ++nt) {
        const int n0 = nt * 128;
        float c[4][4][4];
        #pragma unroll
        for (int i = 0; i < 4; ++i)
            #pragma unroll
            for (int j = 0; j < 4; ++j)
                c[i][j][0] = c[i][j][1] = c[i][j][2] = c[i][j][3] = 0.f;

        for (int s = 0; s < 12; ++s) {
            __syncthreads();
            {
                const uint4* src = (const uint4*)(g_wh
                    + (size_t)(n0 + bs_n) * 192 + s * 16 + bs_kb * 4);
                uint4 v0 = src[0];
                uint4 v1 = src[1];
                uint32_t dst = bbase + (uint32_t)(bs_n * (BSTH * 2) + bs_kb * 16);
                asm volatile("st.shared.v4.b32 [%0], {%1,%2,%3,%4};"
                             :: "r"(dst), "r"(v0.x), "r"(v0.y), "r"(v0.z), "r"(v0.w));
                asm volatile("st.shared.v4.b32 [%0], {%1,%2,%3,%4};"
                             :: "r"(dst + 16), "r"(v1.x), "r"(v1.y), "r"(v1.z), "r"(v1.w));
            }
            __syncthreads();

            #pragma unroll
            for (int kc = 0; kc < 2; ++kc) {
                uint32_t a[4][4], bb[2][4];
                const uint32_t a_base = abase + a_lane
                    + (uint32_t)((s * 32 + kc * 16) * (ASTH * 2));
                #pragma unroll
                for (int i = 0; i < 4; ++i)
                    ldsm_x4_t(a[i][0], a[i][1], a[i][2], a[i][3],
                              a_base + (uint32_t)(i * 32));
                const uint32_t b_base = bbase + b_lane + (uint32_t)(kc * 32);
                #pragma unroll
                for (int jp = 0; jp < 2; ++jp)
                    ldsm_x4(bb[jp][0], bb[jp][1], bb[jp][2], bb[jp][3],
                            b_base + (uint32_t)(jp * 16 * (BSTH * 2)));
                #pragma unroll
                for (int i = 0; i < 4; ++i)
                    #pragma unroll
                    for (int j = 0; j < 4; ++j) {
                        const int jp = j >> 1, lo = (j & 1) * 2;
                        mma_f16(c[i][j][0], c[i][j][1], c[i][j][2], c[i][j][3],
                                a[i][0], a[i][1], a[i][2], a[i][3],
                                bb[jp][lo], bb[jp][lo + 1]);
                    }
            }
        }

        // ---- Epilogue: bias + q-scale, pack fp16, quad transpose, STG.128 ----
        // Pre-transpose: lane(lq,lr) holds, per j, cols (j*8 + lr*2, +1).
        // After 3 shfl.xor rounds: v[s] = tile-lr pair from quad-lane s
        //   -> uint4 = 8 contiguous halves of tile lr; quad covers 64B/row.
        const float qsc = (n0 < 384) ? 0.10206207261596577f : 1.0f;
        float2 bv[4];
        #pragma unroll
        for (int j = 0; j < 4; ++j)
            bv[j] = *(const float2*)(bias + n0 + nw * 32 + j * 8 + lr * 2);

        const int gcol = (n0 + nw * 32 + lr * 8) >> 1;   // word offset of 16B chunk
        #pragma unroll
        for (int i = 0; i < 4; ++i) {
            uint32_t v0[4], v1[4];
            #pragma unroll
            for (int j = 0; j < 4; ++j) {
                v0[j] = pack_h2((c[i][j][0] + bv[j].x) * qsc,
                                (c[i][j][1] + bv[j].y) * qsc);
                v1[j] = pack_h2((c[i][j][2] + bv[j].x) * qsc,
                                (c[i][j][3] + bv[j].y) * qsc);
            }
            #pragma unroll
            for (int m = 1; m < 4; ++m) {
                v0[lr ^ m] = __shfl_xor_sync(0xffffffffu, v0[lr ^ m], m);
                v1[lr ^ m] = __shfl_xor_sync(0xffffffffu, v1[lr ^ m], m);
            }
            const int gm0 = m0 + mw * 64 + i * 16 + lq;
            *(uint4*)(g_qkvh + (size_t)gm0 * 576 + gcol) =
                make_uint4(v0[0], v0[1], v0[2], v0[3]);
            *(uint4*)(g_qkvh + (size_t)(gm0 + 8) * 576 + gcol) =
                make_uint4(v1[0], v1[1], v1[2], v1[3]);
        }
    }
}

// ---------------------------------------------------------------------------
// Kernel 2: tensor-core windowed attention (fp16 input; pure-copy prologue)
// ---------------------------------------------------------------------------
#define ROWB 208                      // bytes per Q/K/V row (104 halves)
#define MATB (64 * ROWB)              // 13312 bytes per matrix
#define AT_SMEM (3 * MATB)            // 39936

__global__ void __launch_bounds__(128) attn_tc(float* __restrict__ out)
{
    extern __shared__ char smem[];
    const uint32_t qb = smem_u32(smem);
    const uint32_t kb = qb + MATB;
    const uint32_t vb = kb + MATB;
    uint32_t* smw = (uint32_t*)smem;
    float* osm = (float*)smem;        // reused AFTER AV (post-sync)

    const int tid  = threadIdx.x;
    const int wrp  = tid >> 5;
    const int lid  = tid & 31;
    const int lam  = lid & 3;
    const int win  = blockIdx.x;
    const int head = blockIdx.y;
    const int b    = win >> 10;
    const int wh   = (win >> 5) & 31;
    const int ww   = win & 31;

    // Zero pad rows 49..63 of Q/K/V (52 words per row)
    for (int i = tid; i < 2340; i += 128) {
        int arr = i / 780, rem = i % 780;
        smw[arr * 3328 + (49 + rem / 52) * 52 + (rem % 52)] = 0u;
    }

    // Load Q/K/V: pure uint4 copy (q already scaled, all fp16)
    for (int e = tid; e < 1764; e += 128) {
        int tok = e / 36, r = e % 36;
        int seg = r / 12, f4 = r % 12;
        const uint4* src = (const uint4*)(g_qkvh
            + ((size_t)b * HWB + (wh * 7 + tok / 7) * W_IMG + ww * 7 + tok % 7) * 576
            + seg * 192 + head * 48 + f4 * 4);
        uint4 v = *src;
        uint32_t dst = qb + (uint32_t)(seg * MATB + tok * ROWB + f4 * 16);
        asm volatile("st.shared.v4.b32 [%0], {%1,%2,%3,%4};"
                     :: "r"(dst), "r"(v.x), "r"(v.y), "r"(v.z), "r"(v.w));
    }
    __syncthreads();

    // ---- Scores: S[q][key] = Q . K ----
    const int q0 = wrp * 16;
    const uint32_t a_addr = qb + (uint32_t)((q0 + (lid & 15)) * ROWB + (lid >> 4) * 16);
    const uint32_t k_rsel = (uint32_t)((((lid >> 4) & 1) * 8 + (lid & 7)) * ROWB
                                       + ((lid >> 3) & 1) * 16);
    float sc[7][4];
    #pragma unroll
    for (int t = 0; t < 7; ++t)
        sc[t][0] = sc[t][1] = sc[t][2] = sc[t][3] = 0.f;

    #pragma unroll
    for (int s = 0; s < 6; ++s) {
        uint32_t a0, a1, a2, a3;
        ldsm_x4(a0, a1, a2, a3, a_addr + (uint32_t)(s * 32));
        #pragma unroll
        for (int np = 0; np < 4; ++np) {
            uint32_t r0, r1, r2, r3;
            ldsm_x4(r0, r1, r2, r3, kb + k_rsel + (uint32_t)(np * 16 * ROWB + s * 32));
            mma_f16(sc[2*np][0], sc[2*np][1], sc[2*np][2], sc[2*np][3],
                    a0, a1, a2, a3, r0, r1);
            if (np < 3)
                mma_f16(sc[2*np+1][0], sc[2*np+1][1], sc[2*np+1][2], sc[2*np+1][3],
                        a0, a1, a2, a3, r2, r3);
        }
    }

    // ---- Softmax in registers ----
    float mx0 = -1e30f, mx1 = -1e30f;
    #pragma unroll
    for (int t = 0; t < 6; ++t) {
        mx0 = fmaxf(mx0, fmaxf(sc[t][0], sc[t][1]));
        mx1 = fmaxf(mx1, fmaxf(sc[t][2], sc[t][3]));
    }
    if (lam == 0) { mx0 = fmaxf(mx0, sc[6][0]); mx1 = fmaxf(mx1, sc[6][2]); }
    mx0 = fmaxf(mx0, __shfl_xor_sync(0xffffffffu, mx0, 1));
    mx0 = fmaxf(mx0, __shfl_xor_sync(0xffffffffu, mx0, 2));
    mx1 = fmaxf(mx1, __shfl_xor_sync(0xffffffffu, mx1, 1));
    mx1 = fmaxf(mx1, __shfl_xor_sync(0xffffffffu, mx1, 2));

    float pr[7][4];
    float sum0 = 0.f, sum1 = 0.f;
    #pragma unroll
    for (int t = 0; t < 6; ++t) {
        pr[t][0] = __expf(sc[t][0] - mx0);
        pr[t][1] = __expf(sc[t][1] - mx0);
        pr[t][2] = __expf(sc[t][2] - mx1);
        pr[t][3] = __expf(sc[t][3] - mx1);
        sum0 += pr[t][0] + pr[t][1];
        sum1 += pr[t][2] + pr[t][3];
    }
    pr[6][0] = (lam == 0) ? __expf(sc[6][0] - mx0) : 0.f;
    pr[6][1] = 0.f;
    pr[6][2] = (lam == 0) ? __expf(sc[6][2] - mx1) : 0.f;
    pr[6][3] = 0.f;
    sum0 += pr[6][0];
    sum1 += pr[6][2];
    sum0 += __shfl_xor_sync(0xffffffffu, sum0, 1);
    sum0 += __shfl_xor_sync(0xffffffffu, sum0, 2);
    sum1 += __shfl_xor_sync(0xffffffffu, sum1, 1);
    sum1 += __shfl_xor_sync(0xffffffffu, sum1, 2);
    const float inv0 = 1.f / sum0;
    const float inv1 = 1.f / sum1;

    // ---- AV: out = P . V ----
    float co[12][4];
    #pragma unroll
    for (int t = 0; t < 12; ++t)
        co[t][0] = co[t][1] = co[t][2] = co[t][3] = 0.f;

    const uint32_t v_rsel = (uint32_t)((lid & 15) * ROWB + ((lid >> 4) & 1) * 16);
    #pragma unroll
    for (int t = 0; t < 4; ++t) {
        uint32_t a0 = pack_h2(pr[2*t][0], pr[2*t][1]);
        uint32_t a1 = pack_h2(pr[2*t][2], pr[2*t][3]);
        uint32_t a2 = 0u, a3 = 0u;
        if (t < 3) {
            a2 = pack_h2(pr[2*t+1][0], pr[2*t+1][1]);
            a3 = pack_h2(pr[2*t+1][2], pr[2*t+1][3]);
        }
        #pragma unroll
        for (int np = 0; np < 6; ++np) {
            uint32_t r0, r1, r2, r3;
            ldsm_x4_t(r0, r1, r2, r3, vb + v_rsel + (uint32_t)(t * 16 * ROWB + np * 32));
            mma_f16(co[2*np][0], co[2*np][1], co[2*np][2], co[2*np][3],
                    a0, a1, a2, a3, r0, r1);
            mma_f16(co[2*np+1][0], co[2*np+1][1], co[2*np+1][2], co[2*np+1][3],
                    a0, a1, a2, a3, r2, r3);
        }
    }
    __syncthreads();

    // ---- Stage normalized output rows to osm[49][96] ----
    {
        const int r   = lid >> 2;
        const int rg0 = q0 + r;
        const int rg8 = q0 + r + 8;
        #pragma unroll
        for (int nt = 0; nt < 12; ++nt) {
            const int d = nt * 8 + 2 * lam;
            if (rg0 < 49)
                *(float2*)(osm + rg0 * 96 + d) =
                    make_float2(co[nt][0] * inv0, co[nt][1] * inv0);
            if (rg8 < 49)
                *(float2*)(osm + rg8 * 96 + d) =
                    make_float2(co[nt][2] * inv1, co[nt][3] * inv1);
        }
    }
    __syncthreads();

    // ---- Coalesced-ish global write (w-contiguous runs of 7) ----
    for (int e = tid; e < 4704; e += 128) {
        int tok = e % 49, d = e / 49;
        out[(((size_t)b * C_DIM + head * HD + d) * H_IMG + wh * 7 + tok / 7) * W_IMG
            + ww * 7 + tok % 7] = osm[tok * 96 + d];
    }
}

// ---------------------------------------------------------------------------
extern "C" void kernel_launch(void* const* d_in, const int* in_sizes, int n_in,
                              void* d_out, int out_size)
{
    const float* x    = (const float*)d_in[0];
    const float* w    = (const float*)d_in[1];
    const float* bias = (const float*)d_in[2];
    float* out        = (float*)d_out;

    cudaFuncSetAttribute(qkv_mma, cudaFuncAttributeMaxDynamicSharedMemorySize,
                         (int)QKV_SMEM);
    cudaFuncSetAttribute(attn_tc, cudaFuncAttributeMaxDynamicSharedMemorySize,
                         (int)AT_SMEM);

    wconv<<<432, 256>>>(w);
    qkv_mma<<<M_TOT / 128, 256, QKV_SMEM>>>(x, bias);
    attn_tc<<<dim3(B_SZ * 32 * 32, NHEADS), 128, AT_SMEM>>>(out);
}

// round 10
// speedup vs baseline: 1.1698x; 1.0729x over previous
#include <cuda_runtime.h>
#include <cstdint>

// Problem constants
#define C_DIM   384
#define N_DIM   1152
#define B_SZ    8
#define H_IMG   224
#define W_IMG   224
#define HWB     50176
#define M_TOT   401408
#define HD      96
#define NHEADS  4

// QKV scratch in fp16 (half2 words): [M_TOT][576 words]; q pre-scaled by 96^-0.5
__device__ uint32_t g_qkvh[(size_t)M_TOT * 576];
// Pre-converted W in fp16 (half2 words): [1152][384] halves
__device__ uint32_t g_wh[221184];

__device__ __forceinline__ uint32_t pack_h2(float lo, float hi) {
    uint32_t r;
    asm("cvt.rn.f16x2.f32 %0, %1, %2;" : "=r"(r) : "f"(hi), "f"(lo));
    return r;   // d<15:0> = lo, d<31:16> = hi
}

__device__ __forceinline__ uint32_t smem_u32(const void* p) {
    uint32_t a;
    asm("{ .reg .u64 t; cvta.to.shared.u64 t, %1; cvt.u32.u64 %0, t; }"
        : "=r"(a) : "l"(p));
    return a;
}

#define CP_ASYNC16(dst, src) \
    asm volatile("cp.async.cg.shared.global [%0], [%1], 16;" \
                 :: "r"(dst), "l"(src) : "memory")
#define CP_COMMIT()  asm volatile("cp.async.commit_group;" ::: "memory")
#define CP_WAIT0()   asm volatile("cp.async.wait_group 0;" ::: "memory")

__device__ __forceinline__ void ldsm_x4(uint32_t& r0, uint32_t& r1,
                                        uint32_t& r2, uint32_t& r3, uint32_t a) {
    asm volatile("ldmatrix.sync.aligned.m8n8.x4.shared.b16 {%0,%1,%2,%3}, [%4];"
                 : "=r"(r0), "=r"(r1), "=r"(r2), "=r"(r3) : "r"(a));
}
__device__ __forceinline__ void ldsm_x4_t(uint32_t& r0, uint32_t& r1,
                                          uint32_t& r2, uint32_t& r3, uint32_t a) {
    asm volatile("ldmatrix.sync.aligned.m8n8.x4.trans.shared.b16 {%0,%1,%2,%3}, [%4];"
                 : "=r"(r0), "=r"(r1), "=r"(r2), "=r"(r3) : "r"(a));
}

__device__ __forceinline__ void mma_f16(float& c0, float& c1, float& c2, float& c3,
                                        uint32_t a0, uint32_t a1, uint32_t a2, uint32_t a3,
                                        uint32_t b0, uint32_t b1) {
    asm volatile(
        "mma.sync.aligned.m16n8k16.row.col.f32.f16.f16.f32 "
        "{%0,%1,%2,%3}, {%4,%5,%6,%7}, {%8,%9}, {%0,%1,%2,%3};"
        : "+f"(c0), "+f"(c1), "+f"(c2), "+f"(c3)
        : "r"(a0), "r"(a1), "r"(a2), "r"(a3), "r"(b0), "r"(b1));
}

// ---------------------------------------------------------------------------
// Kernel 0: one-time W fp32 -> fp16 conversion
// ---------------------------------------------------------------------------
__global__ void __launch_bounds__(256) wconv(const float* __restrict__ w)
{
    int i = blockIdx.x * 256 + threadIdx.x;
    if (i < 110592) {
        float4 v = ((const float4*)w)[i];
        uint2 o;
        o.x = pack_h2(v.x, v.y);
        o.y = pack_h2(v.z, v.w);
        ((uint2*)g_wh)[i] = o;
    }
}

// ---------------------------------------------------------------------------
// Kernel 1: QKV GEMM (Round-9 structure; B stages via cp.async)
// ---------------------------------------------------------------------------
#define ASTH 136
#define BSTH 40
#define AS_BYTES (384 * ASTH * 2)
#define QKV_SMEM (AS_BYTES + 128 * BSTH * 2)

__global__ void __launch_bounds__(256, 2) qkv_mma(
    const float* __restrict__ x,
    const float* __restrict__ bias)
{
    extern __shared__ char smem[];
    const uint32_t abase = smem_u32(smem);
    const uint32_t bbase = abase + AS_BYTES;

    const int tid = threadIdx.x;
    const int wid = tid >> 5;
    const int lid = tid & 31;
    const int mw  = wid & 1;
    const int nw  = wid >> 1;
    const int lq  = lid >> 2;
    const int lr  = lid & 3;

    const int m0 = blockIdx.x * 128;
    const int b  = m0 / HWB;
    const float* xb = x + (size_t)b * C_DIM * HWB + (m0 - b * HWB);

    for (int i = tid; i < 12288; i += 256) {
        int k = i >> 5, m4 = i & 31;
        float4 v = *(const float4*)(xb + (size_t)k * HWB + m4 * 4);
        uint32_t h0 = pack_h2(v.x, v.y);
        uint32_t h1 = pack_h2(v.z, v.w);
        uint32_t dst = abase + (uint32_t)(k * ASTH + m4 * 4) * 2;
        asm volatile("st.shared.v2.b32 [%0], {%1,%2};" :: "r"(dst), "r"(h0), "r"(h1));
    }

    const uint32_t a_lane = (uint32_t)(((lid & 7) + ((lid >> 4) & 1) * 8) * (ASTH * 2)
                                       + (mw * 64 + ((lid >> 3) & 1) * 8) * 2);
    const uint32_t b_lane = (uint32_t)((nw * 32 + ((lid >> 4) & 1) * 8 + (lid & 7)) * (BSTH * 2)
                                       + ((lid >> 3) & 1) * 16);

    const int bs_n  = tid >> 1;
    const int bs_kb = (tid & 1) * 2;
    const uint32_t bs_dst = bbase + (uint32_t)(bs_n * (BSTH * 2) + bs_kb * 16);

    for (int nt = 0; nt < 9; ++nt) {
        const int n0 = nt * 128;
        float c[4][4][4];
        #pragma unroll
        for (int i = 0; i < 4; ++i)
            #pragma unroll
            for (int j = 0; j < 4; ++j)
                c[i][j][0] = c[i][j][1] = c[i][j][2] = c[i][j][3] = 0.f;

        for (int s = 0; s < 12; ++s) {
            __syncthreads();            // prior-stage readers done
            {
                const uint32_t* src = g_wh + (size_t)(n0 + bs_n) * 192
                                      + s * 16 + bs_kb * 4;
                CP_ASYNC16(bs_dst,      (const void*)src);
                CP_ASYNC16(bs_dst + 16, (const void*)(src + 4));
                CP_COMMIT();
                CP_WAIT0();
            }
            __syncthreads();

            #pragma unroll
            for (int kc = 0; kc < 2; ++kc) {
                uint32_t a[4][4], bb[2][4];
                const uint32_t a_base = abase + a_lane
                    + (uint32_t)((s * 32 + kc * 16) * (ASTH * 2));
                #pragma unroll
                for (int i = 0; i < 4; ++i)
                    ldsm_x4_t(a[i][0], a[i][1], a[i][2], a[i][3],
                              a_base + (uint32_t)(i * 32));
                const uint32_t b_base = bbase + b_lane + (uint32_t)(kc * 32);
                #pragma unroll
                for (int jp = 0; jp < 2; ++jp)
                    ldsm_x4(bb[jp][0], bb[jp][1], bb[jp][2], bb[jp][3],
                            b_base + (uint32_t)(jp * 16 * (BSTH * 2)));
                #pragma unroll
                for (int i = 0; i < 4; ++i)
                    #pragma unroll
                    for (int j = 0; j < 4; ++j) {
                        const int jp = j >> 1, lo = (j & 1) * 2;
                        mma_f16(c[i][j][0], c[i][j][1], c[i][j][2], c[i][j][3],
                                a[i][0], a[i][1], a[i][2], a[i][3],
                                bb[jp][lo], bb[jp][lo + 1]);
                    }
            }
        }

        // ---- Epilogue: bias + q-scale, pack fp16, quad transpose, STG.128 ----
        const float qsc = (n0 < 384) ? 0.10206207261596577f : 1.0f;
        float2 bv[4];
        #pragma unroll
        for (int j = 0; j < 4; ++j)
            bv[j] = *(const float2*)(bias + n0 + nw * 32 + j * 8 + lr * 2);

        const int gcol = (n0 + nw * 32 + lr * 8) >> 1;
        #pragma unroll
        for (int i = 0; i < 4; ++i) {
            uint32_t v0[4], v1[4];
            #pragma unroll
            for (int j = 0; j < 4; ++j) {
                v0[j] = pack_h2((c[i][j][0] + bv[j].x) * qsc,
                                (c[i][j][1] + bv[j].y) * qsc);
                v1[j] = pack_h2((c[i][j][2] + bv[j].x) * qsc,
                                (c[i][j][3] + bv[j].y) * qsc);
            }
            #pragma unroll
            for (int m = 1; m < 4; ++m) {
                v0[lr ^ m] = __shfl_xor_sync(0xffffffffu, v0[lr ^ m], m);
                v1[lr ^ m] = __shfl_xor_sync(0xffffffffu, v1[lr ^ m], m);
            }
            const int gm0 = m0 + mw * 64 + i * 16 + lq;
            *(uint4*)(g_qkvh + (size_t)gm0 * 576 + gcol) =
                make_uint4(v0[0], v0[1], v0[2], v0[3]);
            *(uint4*)(g_qkvh + (size_t)(gm0 + 8) * 576 + gcol) =
                make_uint4(v1[0], v1[1], v1[2], v1[3]);
        }
    }
}

// ---------------------------------------------------------------------------
// Kernel 2: tensor-core windowed attention (cp.async prologue)
// ---------------------------------------------------------------------------
#define ROWB 208                      // bytes per Q/K/V row (104 halves)
#define MATB (64 * ROWB)              // 13312 bytes per matrix
#define AT_SMEM (3 * MATB)            // 39936

__global__ void __launch_bounds__(128) attn_tc(float* __restrict__ out)
{
    extern __shared__ char smem[];
    const uint32_t qb = smem_u32(smem);
    const uint32_t kb = qb + MATB;
    const uint32_t vb = kb + MATB;
    uint32_t* smw = (uint32_t*)smem;
    float* osm = (float*)smem;        // reused AFTER AV (post-sync)

    const int tid  = threadIdx.x;
    const int wrp  = tid >> 5;
    const int lid  = tid & 31;
    const int lam  = lid & 3;
    const int win  = blockIdx.x;
    const int head = blockIdx.y;
    const int b    = win >> 10;
    const int wh   = (win >> 5) & 31;
    const int ww   = win & 31;

    // Kick off all Q/K/V loads first: fire-and-forget cp.async (16B each)
    // 49 tokens x 3 segs x 12 uint4 = 1764 chunks
    #pragma unroll
    for (int p = 0; p < 14; ++p) {
        int e = p * 128 + tid;
        if (e < 1764) {
            int tok = e / 36, r = e % 36;
            int seg = r / 12, f4 = r % 12;
            const uint32_t* src = g_qkvh
                + ((size_t)b * HWB + (wh * 7 + tok / 7) * W_IMG + ww * 7 + tok % 7) * 576
                + seg * 192 + head * 48 + f4 * 4;
            uint32_t dst = qb + (uint32_t)(seg * MATB + tok * ROWB + f4 * 16);
            CP_ASYNC16(dst, (const void*)src);
        }
    }
    CP_COMMIT();

    // Zero pad rows 49..63 of Q/K/V while loads fly (52 words per row)
    for (int i = tid; i < 2340; i += 128) {
        int arr = i / 780, rem = i % 780;
        smw[arr * 3328 + (49 + rem / 52) * 52 + (rem % 52)] = 0u;
    }
    CP_WAIT0();
    __syncthreads();

    // ---- Scores: S[q][key] = Q . K ----
    const int q0 = wrp * 16;
    const uint32_t a_addr = qb + (uint32_t)((q0 + (lid & 15)) * ROWB + (lid >> 4) * 16);
    const uint32_t k_rsel = (uint32_t)((((lid >> 4) & 1) * 8 + (lid & 7)) * ROWB
                                       + ((lid >> 3) & 1) * 16);
    float sc[7][4];
    #pragma unroll
    for (int t = 0; t < 7; ++t)
        sc[t][0] = sc[t][1] = sc[t][2] = sc[t][3] = 0.f;

    #pragma unroll
    for (int s = 0; s < 6; ++s) {
        uint32_t a0, a1, a2, a3;
        ldsm_x4(a0, a1, a2, a3, a_addr + (uint32_t)(s * 32));
        #pragma unroll
        for (int np = 0; np < 4; ++np) {
            uint32_t r0, r1, r2, r3;
            ldsm_x4(r0, r1, r2, r3, kb + k_rsel + (uint32_t)(np * 16 * ROWB + s * 32));
            mma_f16(sc[2*np][0], sc[2*np][1], sc[2*np][2], sc[2*np][3],
                    a0, a1, a2, a3, r0, r1);
            if (np < 3)
                mma_f16(sc[2*np+1][0], sc[2*np+1][1], sc[2*np+1][2], sc[2*np+1][3],
                        a0, a1, a2, a3, r2, r3);
        }
    }

    // ---- Softmax in registers ----
    float mx0 = -1e30f, mx1 = -1e30f;
    #pragma unroll
    for (int t = 0; t < 6; ++t) {
        mx0 = fmaxf(mx0, fmaxf(sc[t][0], sc[t][1]));
        mx1 = fmaxf(mx1, fmaxf(sc[t][2], sc[t][3]));
    }
    if (lam == 0) { mx0 = fmaxf(mx0, sc[6][0]); mx1 = fmaxf(mx1, sc[6][2]); }
    mx0 = fmaxf(mx0, __shfl_xor_sync(0xffffffffu, mx0, 1));
    mx0 = fmaxf(mx0, __shfl_xor_sync(0xffffffffu, mx0, 2));
    mx1 = fmaxf(mx1, __shfl_xor_sync(0xffffffffu, mx1, 1));
    mx1 = fmaxf(mx1, __shfl_xor_sync(0xffffffffu, mx1, 2));

    float pr[7][4];
    float sum0 = 0.f, sum1 = 0.f;
    #pragma unroll
    for (int t = 0; t < 6; ++t) {
        pr[t][0] = __expf(sc[t][0] - mx0);
        pr[t][1] = __expf(sc[t][1] - mx0);
        pr[t][2] = __expf(sc[t][2] - mx1);
        pr[t][3] = __expf(sc[t][3] - mx1);
        sum0 += pr[t][0] + pr[t][1];
        sum1 += pr[t][2] + pr[t][3];
    }
    pr[6][0] = (lam == 0) ? __expf(sc[6][0] - mx0) : 0.f;
    pr[6][1] = 0.f;
    pr[6][2] = (lam == 0) ? __expf(sc[6][2] - mx1) : 0.f;
    pr[6][3] = 0.f;
    sum0 += pr[6][0];
    sum1 += pr[6][2];
    sum0 += __shfl_xor_sync(0xffffffffu, sum0, 1);
    sum0 += __shfl_xor_sync(0xffffffffu, sum0, 2);
    sum1 += __shfl_xor_sync(0xffffffffu, sum1, 1);
    sum1 += __shfl_xor_sync(0xffffffffu, sum1, 2);
    const float inv0 = 1.f / sum0;
    const float inv1 = 1.f / sum1;

    // ---- AV: out = P . V ----
    float co[12][4];
    #pragma unroll
    for (int t = 0; t < 12; ++t)
        co[t][0] = co[t][1] = co[t][2] = co[t][3] = 0.f;

    const uint32_t v_rsel = (uint32_t)((lid & 15) * ROWB + ((lid >> 4) & 1) * 16);
    #pragma unroll
    for (int t = 0; t < 4; ++t) {
        uint32_t a0 = pack_h2(pr[2*t][0], pr[2*t][1]);
        uint32_t a1 = pack_h2(pr[2*t][2], pr[2*t][3]);
        uint32_t a2 = 0u, a3 = 0u;
        if (t < 3) {
            a2 = pack_h2(pr[2*t+1][0], pr[2*t+1][1]);
            a3 = pack_h2(pr[2*t+1][2], pr[2*t+1][3]);
        }
        #pragma unroll
        for (int np = 0; np < 6; ++np) {
            uint32_t r0, r1, r2, r3;
            ldsm_x4_t(r0, r1, r2, r3, vb + v_rsel + (uint32_t)(t * 16 * ROWB + np * 32));
            mma_f16(co[2*np][0], co[2*np][1], co[2*np][2], co[2*np][3],
                    a0, a1, a2, a3, r0, r1);
            mma_f16(co[2*np+1][0], co[2*np+1][1], co[2*np+1][2], co[2*np+1][3],
                    a0, a1, a2, a3, r2, r3);
        }
    }
    __syncthreads();

    // ---- Stage normalized output rows to osm[49][96] ----
    {
        const int r   = lid >> 2;
        const int rg0 = q0 + r;
        const int rg8 = q0 + r + 8;
        #pragma unroll
        for (int nt = 0; nt < 12; ++nt) {
            const int d = nt * 8 + 2 * lam;
            if (rg0 < 49)
                *(float2*)(osm + rg0 * 96 + d) =
                    make_float2(co[nt][0] * inv0, co[nt][1] * inv0);
            if (rg8 < 49)
                *(float2*)(osm + rg8 * 96 + d) =
                    make_float2(co[nt][2] * inv1, co[nt][3] * inv1);
        }
    }
    __syncthreads();

    // ---- Coalesced-ish global write (w-contiguous runs of 7) ----
    for (int e = tid; e < 4704; e += 128) {
        int tok = e % 49, d = e / 49;
        out[(((size_t)b * C_DIM + head * HD + d) * H_IMG + wh * 7 + tok / 7) * W_IMG
            + ww * 7 + tok % 7] = osm[tok * 96 + d];
    }
}

// ---------------------------------------------------------------------------
extern "C" void kernel_launch(void* const* d_in, const int* in_sizes, int n_in,
                              void* d_out, int out_size)
{
    const float* x    = (const float*)d_in[0];
    const float* w    = (const float*)d_in[1];
    const float* bias = (const float*)d_in[2];
    float* out        = (float*)d_out;

    cudaFuncSetAttribute(qkv_mma, cudaFuncAttributeMaxDynamicSharedMemorySize,
                         (int)QKV_SMEM);
    cudaFuncSetAttribute(attn_tc, cudaFuncAttributeMaxDynamicSharedMemorySize,
                         (int)AT_SMEM);

    wconv<<<432, 256>>>(w);
    qkv_mma<<<M_TOT / 128, 256, QKV_SMEM>>>(x, bias);
    attn_tc<<<dim3(B_SZ * 32 * 32, NHEADS), 128, AT_SMEM>>>(out);
}